// round 1
// baseline (speedup 1.0000x reference)
#include <cuda_runtime.h>
#include <math.h>

// ---------------- scratch (static device globals; no allocation) ----------------
__device__ float g_h1[512 * 1024];
__device__ float g_h2[512 * 128];
__device__ float g_hidden[512 * 4096];      // [b][o*64+d]
__device__ float g_cf[64 * 64 * 256];       // [x][y][f*32+h]
__device__ float g_s[64 * 64];
__device__ float g_cfs[64 * 64 * 32];       // [x][y][h]
__device__ float g_csum[64 * 32];
__device__ float g_att[64 * 2048];          // [o][i*32+g]
__device__ float g_att2[64 * 2048];         // [o][j]
__device__ float g_Cpart[8 * 64 * 2112];
__device__ float g_C[64 * 2112];            // [o][e]

__device__ __forceinline__ float eluf(float x) { return x > 0.f ? x : expm1f(x); }

// ---------------- precompute: coef / attention chain (batch-independent) --------

// cf[x,y,f,h] = elu(coef_m[x,y,f]*coef_nn_W[f,h,0] + coef_nn_b[f,h]);  s = sum exp(elu(cf))
__global__ __launch_bounds__(256) void k_cf(const float* __restrict__ cm,
                                            const float* __restrict__ cw,
                                            const float* __restrict__ cb) {
    int pair = blockIdx.x;          // x*64+y
    int t = threadIdx.x;
    int f = t >> 5, h = t & 31;
    float m = cm[pair * 8 + f];
    float v = eluf(m * cw[f * 32 + h] + cb[f * 32 + h]);
    g_cf[pair * 256 + t] = v;
    __shared__ float red[256];
    red[t] = expf(eluf(v));
    __syncthreads();
    for (int s = 128; s > 0; s >>= 1) {
        if (t < s) red[t] += red[t + s];
        __syncthreads();
    }
    if (t == 0) g_s[pair] = red[0];
}

// cfs[x,y,g] = elu( (1/F) * sum_f elu( exp(elu(cf[f,g])) * (sum_h cf[f,h]*caw[f,g,h]) / s ) )
__global__ __launch_bounds__(256) void k_cfs(const float* __restrict__ caw) {
    int pair = blockIdx.x;
    int t = threadIdx.x;
    int f = t >> 5, g = t & 31;
    __shared__ float sc[256];
    __shared__ float sp[256];
    sc[t] = g_cf[pair * 256 + t];
    __syncthreads();
    float lin = 0.f;
#pragma unroll
    for (int h = 0; h < 32; h++) lin += sc[f * 32 + h] * caw[f * 1024 + g * 32 + h];
    float E = expf(eluf(sc[f * 32 + g]));
    sp[t] = eluf(E * lin / g_s[pair]);
    __syncthreads();
    if (t < 32) {
        float sum = 0.f;
#pragma unroll
        for (int ff = 0; ff < 8; ff++) sum += sp[ff * 32 + t];
        g_cfs[pair * 32 + t] = eluf(sum * 0.125f);
    }
}

// coef_sum[x,h] = sum_y exp(elu(cfs[x,y,h]))
__global__ void k_csum() {
    int x = blockIdx.x, h = threadIdx.x;
    float s = 0.f;
    for (int y = 0; y < 64; y++) s += expf(eluf(g_cfs[(x * 64 + y) * 32 + h]));
    g_csum[x * 32 + h] = s;
}

// att[o, i*32+g] = (exp(elu(cfs[o,i,g]))/csum[o,g]) * (sum_h cfs[o,i,h]*oaw[i,g,h])
__global__ void k_att(const float* __restrict__ oaw) {
    int blk = blockIdx.x;           // o*64+i
    int o = blk >> 6, i = blk & 63;
    int g = threadIdx.x;
    __shared__ float sc[32];
    sc[g] = g_cfs[blk * 32 + g];
    __syncthreads();
    float lin = 0.f;
#pragma unroll
    for (int h = 0; h < 32; h++) lin += sc[h] * oaw[i * 1024 + g * 32 + h];
    float p2 = expf(eluf(sc[g])) / g_csum[o * 32 + g];
    g_att[o * 2048 + i * 32 + g] = p2 * lin;
}

// att2[o,j] = sum_p Wnt[o,p] * att[p,j]
__global__ __launch_bounds__(256) void k_att2(const float* __restrict__ wnt) {
    int idx = blockIdx.x * 256 + threadIdx.x;   // 131072
    int o = idx >> 11, j = idx & 2047;
    float acc = 0.f;
#pragma unroll 8
    for (int p = 0; p < 64; p++) acc += wnt[o * 64 + p] * g_att[p * 2048 + j];
    g_att2[o * 2048 + j] = acc;
}

// deterministic split-K reduce for C
__global__ void k_redC() {
    int i = blockIdx.x * 256 + threadIdx.x;     // 135168
    float s = 0.f;
#pragma unroll
    for (int z = 0; z < 8; z++) s += g_Cpart[z * 135168 + i];
    g_C[i] = s;
}

// ---------------- generic NT sgemm:  C = act(A[M,K] * B[N,K]^T + bias) ----------
// 64x64 tile, 256 threads, 4x4 per thread (strided register tile), K-step 16.
// grid = (N/64, M/64, splitK). When splitK>1, writes partials at zstride*z.
__global__ __launch_bounds__(256) void sgemm_nt(
    const float* __restrict__ A, const float* __restrict__ B,
    const float* __restrict__ bias, float* __restrict__ C,
    int N, int K, int lda, int ldb, int koffB, int relu, int zstride) {
    __shared__ float As[16 * 66];
    __shared__ float Bs[16 * 66];
    int t = threadIdx.x;
    int tx = t & 15, ty = t >> 4;
    int row0 = blockIdx.y * 64, col0 = blockIdx.x * 64;
    int kPer = K / gridDim.z;
    int k0 = blockIdx.z * kPer;
    float acc[4][4] = {};
    for (int kb = 0; kb < kPer; kb += 16) {
#pragma unroll
        for (int q = 0; q < 4; q++) {
            int l = t + q * 256;
            int m = l >> 4, kk = l & 15;
            As[kk * 66 + m] = A[(size_t)(row0 + m) * lda + k0 + kb + kk];
            Bs[kk * 66 + m] = B[(size_t)(col0 + m) * ldb + koffB + k0 + kb + kk];
        }
        __syncthreads();
#pragma unroll
        for (int kk = 0; kk < 16; kk++) {
            float a[4], bv[4];
#pragma unroll
            for (int i = 0; i < 4; i++) a[i] = As[kk * 66 + ty + 16 * i];
#pragma unroll
            for (int j = 0; j < 4; j++) bv[j] = Bs[kk * 66 + tx + 16 * j];
#pragma unroll
            for (int i = 0; i < 4; i++)
#pragma unroll
                for (int j = 0; j < 4; j++) acc[i][j] += a[i] * bv[j];
        }
        __syncthreads();
    }
#pragma unroll
    for (int i = 0; i < 4; i++) {
        int m = row0 + ty + 16 * i;
#pragma unroll
        for (int j = 0; j < 4; j++) {
            int n = col0 + tx + 16 * j;
            float v = acc[i][j];
            if (bias) v += bias[n];
            if (relu) v = fmaxf(v, 0.f);
            C[(size_t)zstride * blockIdx.z + (size_t)m * N + n] = v;
        }
    }
}

// ---------------- fused final: nt1 + y1 GEMM + sigmoid + weighted reduce --------
// one block per batch b. u[o,d] = sum_p Wnt[o,p]*hidden[b,p,d];
// z[b,o] = sum_e w[e]*sigmoid(u[o,:]·G[e,:64] + C[o,e]) + outb;  PReLU.
__global__ __launch_bounds__(256) void k_final(
    const float* __restrict__ Wnt, const float* __restrict__ G,
    const float* __restrict__ wout, const float* __restrict__ outb,
    const float* __restrict__ pa, float* __restrict__ out) {
    __shared__ float sHG[64 * 65];   // hiddens, then reused as G-tile (pad 65 for conflict-free)
    __shared__ float sU[64 * 64];
    __shared__ float sw[2112];
    int b = blockIdx.x;
    int t = threadIdx.x;
    int tx = t & 15, ty = t >> 4;

    const float* hid = g_hidden + (size_t)b * 4096;
#pragma unroll
    for (int q = 0; q < 16; q++) {
        int l = t + q * 256;
        sHG[(l >> 6) * 65 + (l & 63)] = hid[l];
    }
    for (int l = t; l < 2112; l += 256) sw[l] = wout[l];
    __syncthreads();

    // u = Wnt @ H (Wnt from L1/L2; hiddens from smem)
    {
        float acc[4][4] = {};
        for (int p = 0; p < 64; p++) {
            float a[4], bv[4];
#pragma unroll
            for (int i = 0; i < 4; i++) a[i] = Wnt[(ty + 16 * i) * 64 + p];
#pragma unroll
            for (int j = 0; j < 4; j++) bv[j] = sHG[p * 65 + tx + 16 * j];
#pragma unroll
            for (int i = 0; i < 4; i++)
#pragma unroll
                for (int j = 0; j < 4; j++) acc[i][j] += a[i] * bv[j];
        }
        __syncthreads();   // all sHG reads done before reuse; sU stores ordered below
#pragma unroll
        for (int i = 0; i < 4; i++)
#pragma unroll
            for (int j = 0; j < 4; j++) sU[(ty + 16 * i) * 64 + tx + 16 * j] = acc[i][j];
        __syncthreads();
    }

    float zp[4] = {0.f, 0.f, 0.f, 0.f};
    for (int et = 0; et < 33; et++) {
#pragma unroll
        for (int q = 0; q < 16; q++) {
            int l = t + q * 256;
            int e = l >> 6, d = l & 63;
            sHG[e * 65 + d] = G[(size_t)(et * 64 + e) * 2112 + d];
        }
        __syncthreads();
        float yacc[4][4] = {};
#pragma unroll 8
        for (int d = 0; d < 64; d++) {
            float a[4], bv[4];
#pragma unroll
            for (int i = 0; i < 4; i++) a[i] = sU[(ty + 16 * i) * 64 + d];
#pragma unroll
            for (int j = 0; j < 4; j++) bv[j] = sHG[(tx + 16 * j) * 65 + d];
#pragma unroll
            for (int i = 0; i < 4; i++)
#pragma unroll
                for (int j = 0; j < 4; j++) yacc[i][j] += a[i] * bv[j];
        }
#pragma unroll
        for (int i = 0; i < 4; i++) {
            int o = ty + 16 * i;
#pragma unroll
            for (int j = 0; j < 4; j++) {
                int e = et * 64 + tx + 16 * j;
                float y = yacc[i][j] + g_C[o * 2112 + e];
                float sg = 1.f / (1.f + __expf(-y));
                zp[i] += sg * sw[e];
            }
        }
        __syncthreads();
    }

    // cross-thread reduce over the 16 column-groups (reuse sHG)
#pragma unroll
    for (int i = 0; i < 4; i++) sHG[(ty + 16 * i) * 16 + tx] = zp[i];
    __syncthreads();
    if (t < 64) {
        float z = 0.f;
#pragma unroll
        for (int q = 0; q < 16; q++) z += sHG[t * 16 + q];
        z += outb[0];
        float a = pa[0];
        out[b * 64 + t] = z >= 0.f ? z : a * z;
    }
}

// ---------------- launcher ----------------
extern "C" void kernel_launch(void* const* d_in, const int* in_sizes, int n_in,
                              void* d_out, int out_size) {
    const float* x   = (const float*)d_in[0];
    const float* fiW = (const float*)d_in[1];
    const float* fib = (const float*)d_in[2];
    const float* f1W = (const float*)d_in[3];
    const float* f1b = (const float*)d_in[4];
    const float* o1W = (const float*)d_in[5];
    const float* o1b = (const float*)d_in[6];
    const float* cnW = (const float*)d_in[7];
    const float* cnb = (const float*)d_in[8];
    const float* caW = (const float*)d_in[9];
    const float* oaW = (const float*)d_in[10];
    const float* ntW = (const float*)d_in[11];
    const float* gW  = (const float*)d_in[12];
    const float* omW = (const float*)d_in[13];
    const float* omb = (const float*)d_in[14];
    const float* pa  = (const float*)d_in[15];
    const float* cm  = (const float*)d_in[16];
    float* out = (float*)d_out;

    void* p;
    cudaGetSymbolAddress(&p, g_h1);     float* ph1   = (float*)p;
    cudaGetSymbolAddress(&p, g_h2);     float* ph2   = (float*)p;
    cudaGetSymbolAddress(&p, g_hidden); float* phid  = (float*)p;
    cudaGetSymbolAddress(&p, g_att2);   float* patt2 = (float*)p;
    cudaGetSymbolAddress(&p, g_Cpart);  float* pCp   = (float*)p;

    // batch-independent chain
    k_cf<<<4096, 256>>>(cm, cnW, cnb);
    k_cfs<<<4096, 256>>>(caW);
    k_csum<<<64, 32>>>();
    k_att<<<4096, 32>>>(oaW);
    k_att2<<<512, 256>>>(ntW);
    // C = att2 @ G[:,64:]^T   (split-K=8, deterministic reduce)
    sgemm_nt<<<dim3(33, 1, 8), 256>>>(patt2, gW, nullptr, pCp,
                                      2112, 2048, 2048, 2112, 64, 0, 64 * 2112);
    k_redC<<<528, 256>>>();

    // batch trunk
    sgemm_nt<<<dim3(16, 8, 1), 256>>>(x, fiW, fib, ph1, 1024, 2000, 2000, 2000, 0, 1, 0);
    sgemm_nt<<<dim3(2, 8, 1), 256>>>(ph1, f1W, f1b, ph2, 128, 1024, 1024, 1024, 0, 1, 0);
    sgemm_nt<<<dim3(64, 8, 1), 256>>>(ph2, o1W, o1b, phid, 4096, 128, 128, 128, 0, 1, 0);

    // fused final
    k_final<<<512, 256>>>(ntW, gW, omW, omb, pa, out);
}

// round 2
// speedup vs baseline: 1.2275x; 1.2275x over previous
#include <cuda_runtime.h>
#include <math.h>

// ---------------- scratch (static device globals; no allocation) ----------------
__device__ float g_h1[512 * 1024];
__device__ float g_h2[512 * 128];
__device__ float g_hidden[512 * 4096];      // [b][o*64+d]
__device__ float g_cfs[64 * 64 * 32];       // [x][y][h]
__device__ float g_att[64 * 2048];          // [o][i*32+g]
__device__ float g_att2[64 * 2048];         // [o][j]
__device__ float g_Cpart[8 * 64 * 2112];
__device__ float g_C[64 * 2112];            // [o][e]

typedef unsigned long long ull;

__device__ __forceinline__ ull pack2(float x, float y) {
    ull r; asm("mov.b64 %0,{%1,%2};" : "=l"(r) : "f"(x), "f"(y)); return r;
}
__device__ __forceinline__ void ffma2(ull& d, ull a, ull b) {
    asm("fma.rn.f32x2 %0,%1,%2,%0;" : "+l"(d) : "l"(a), "l"(b));
}
__device__ __forceinline__ float2 unpack2(ull v) {
    float2 r; asm("mov.b64 {%0,%1},%2;" : "=f"(r.x), "=f"(r.y) : "l"(v)); return r;
}
__device__ __forceinline__ float eluf(float x) { return x > 0.f ? x : expm1f(x); }
__device__ __forceinline__ float rcpf(float x) {
    float r; asm("rcp.approx.f32 %0,%1;" : "=f"(r) : "f"(x)); return r;
}

// ---------------- fused cf + cfs (batch-independent) ----------------------------
// cf[f,h] = elu(cm*cw+cb); s = sum exp(elu(cf)); p = elu(exp(elu(cf))*lin/s);
// cfs[g] = elu(mean_f p)
__global__ __launch_bounds__(256) void k_cfcfs(const float* __restrict__ cm,
                                               const float* __restrict__ cw,
                                               const float* __restrict__ cb,
                                               const float* __restrict__ caw) {
    int pair = blockIdx.x;          // x*64+y
    int t = threadIdx.x;
    int f = t >> 5, g = t & 31;
    __shared__ float sc[256], red[256], sp[256];
    float m = cm[pair * 8 + f];
    float v = eluf(m * cw[t] + cb[t]);
    sc[t] = v;
    red[t] = expf(eluf(v));
    __syncthreads();
    for (int s = 128; s > 0; s >>= 1) {
        if (t < s) red[t] += red[t + s];
        __syncthreads();
    }
    float s = red[0];
    float lin = 0.f;
#pragma unroll
    for (int h = 0; h < 32; h++) lin += sc[f * 32 + h] * caw[f * 1024 + g * 32 + h];
    float E = expf(eluf(sc[t]));
    sp[t] = eluf(E * lin / s);
    __syncthreads();
    if (t < 32) {
        float sum = 0.f;
#pragma unroll
        for (int ff = 0; ff < 8; ff++) sum += sp[ff * 32 + t];
        g_cfs[pair * 32 + t] = eluf(sum * 0.125f);
    }
}

// ---------------- fused csum + att: block per o --------------------------------
__global__ __launch_bounds__(256) void k_csatt(const float* __restrict__ oaw) {
    int o = blockIdx.x;
    int t = threadIdx.x;
    __shared__ float sc[2048], sE[2048], scs[32];
#pragma unroll
    for (int q = 0; q < 8; q++) {
        int l = t + q * 256;
        float v = g_cfs[o * 2048 + l];
        sc[l] = v;
        sE[l] = expf(eluf(v));
    }
    __syncthreads();
    if (t < 32) {
        float s = 0.f;
        for (int i = 0; i < 64; i++) s += sE[i * 32 + t];
        scs[t] = s;
    }
    __syncthreads();
#pragma unroll
    for (int q = 0; q < 8; q++) {
        int l = t + q * 256;
        int i = l >> 5, g = l & 31;
        float lin = 0.f;
#pragma unroll
        for (int h = 0; h < 32; h++) lin += sc[i * 32 + h] * oaw[i * 1024 + g * 32 + h];
        g_att[o * 2048 + l] = sE[l] / scs[g] * lin;
    }
}

// att2[o,j] = sum_p Wnt[o,p] * att[p,j]
__global__ __launch_bounds__(256) void k_att2(const float* __restrict__ wnt) {
    int idx = blockIdx.x * 256 + threadIdx.x;   // 131072
    int o = idx >> 11, j = idx & 2047;
    float acc = 0.f;
#pragma unroll 8
    for (int p = 0; p < 64; p++) acc += wnt[o * 64 + p] * g_att[p * 2048 + j];
    g_att2[o * 2048 + j] = acc;
}

// deterministic split-K reduce for C
__global__ void k_redC() {
    int i = blockIdx.x * 256 + threadIdx.x;     // 135168
    float s = 0.f;
#pragma unroll
    for (int z = 0; z < 8; z++) s += g_Cpart[z * 135168 + i];
    g_C[i] = s;
}

// ---------------- generic NT sgemm (f32x2 packed):  C = act(A*B^T + bias) ------
// 64x64 tile, 256 threads, 4x4 contiguous per-thread tile, packed pairs on cols.
__global__ __launch_bounds__(256) void sgemm_nt(
    const float* __restrict__ A, const float* __restrict__ B,
    const float* __restrict__ bias, float* __restrict__ C,
    int N, int K, int lda, int ldb, int koffB, int relu, int zstride) {
    __shared__ __align__(16) float As[16 * 68];
    __shared__ __align__(16) float Bs[16 * 68];
    int t = threadIdx.x;
    int tx = t & 15, ty = t >> 4;
    int row0 = blockIdx.y * 64, col0 = blockIdx.x * 64;
    int kPer = K / gridDim.z;
    int k0 = blockIdx.z * kPer;
    ull acc[4][2] = {};
    for (int kb = 0; kb < kPer; kb += 16) {
#pragma unroll
        for (int q = 0; q < 4; q++) {
            int l = t + q * 256;
            int m = l >> 4, kk = l & 15;
            As[kk * 68 + m] = A[(size_t)(row0 + m) * lda + k0 + kb + kk];
            Bs[kk * 68 + m] = B[(size_t)(col0 + m) * ldb + koffB + k0 + kb + kk];
        }
        __syncthreads();
#pragma unroll
        for (int kk = 0; kk < 16; kk++) {
            float4 av = *(const float4*)&As[kk * 68 + ty * 4];
            ulonglong2 bp = *(const ulonglong2*)&Bs[kk * 68 + tx * 4];
            ull a0 = pack2(av.x, av.x), a1 = pack2(av.y, av.y);
            ull a2 = pack2(av.z, av.z), a3 = pack2(av.w, av.w);
            ffma2(acc[0][0], a0, bp.x); ffma2(acc[0][1], a0, bp.y);
            ffma2(acc[1][0], a1, bp.x); ffma2(acc[1][1], a1, bp.y);
            ffma2(acc[2][0], a2, bp.x); ffma2(acc[2][1], a2, bp.y);
            ffma2(acc[3][0], a3, bp.x); ffma2(acc[3][1], a3, bp.y);
        }
        __syncthreads();
    }
#pragma unroll
    for (int i = 0; i < 4; i++) {
        int m = row0 + ty * 4 + i;
#pragma unroll
        for (int j = 0; j < 2; j++) {
            float2 v = unpack2(acc[i][j]);
            int n = col0 + tx * 4 + 2 * j;
            if (bias) { v.x += bias[n]; v.y += bias[n + 1]; }
            if (relu) { v.x = fmaxf(v.x, 0.f); v.y = fmaxf(v.y, 0.f); }
            float* dst = C + (size_t)zstride * blockIdx.z + (size_t)m * N + n;
            dst[0] = v.x;
            dst[1] = v.y;
        }
    }
}

// ---------------- fused final: U + y GEMM + sigmoid + weighted reduce ----------
// block = 2 batches (grid 256). Dynamic smem:
//   sUT [64 d][132]          : U transposed, rows = 2*64 o
//   sA  [64][68]             : phase1 WntT[p][o]; phase2 G-tile [d][e]
//   sB  [64][68] / sw[2112]  : phase1 hidden[p][d]; phase2 wout
__global__ __launch_bounds__(256) void k_final(
    const float* __restrict__ Wnt, const float* __restrict__ G,
    const float* __restrict__ wout, const float* __restrict__ outb,
    const float* __restrict__ pa, float* __restrict__ out) {
    extern __shared__ __align__(16) float smem[];
    float* sUT = smem;              // 8448 floats
    float* sA  = smem + 8448;       // 4352 floats
    float* sB  = smem + 12800;      // 4352 floats
    int t = threadIdx.x;
    int tx = t & 15, ty = t >> 4;
    int bpair = blockIdx.x;

    // stage Wnt transposed: sA[p][o]
#pragma unroll
    for (int q = 0; q < 16; q++) {
        int l = t + q * 256;
        int o = l >> 6, p = l & 63;
        sA[p * 68 + o] = Wnt[l];
    }

    for (int bb = 0; bb < 2; bb++) {
        const float* hid = g_hidden + (size_t)(2 * bpair + bb) * 4096;
#pragma unroll
        for (int q = 0; q < 16; q++) {
            int l = t + q * 256;
            int p = l >> 6, d = l & 63;
            sB[p * 68 + d] = hid[l];
        }
        __syncthreads();
        // U[o][d] = sum_p WntT[p][o] * H[p][d]; thread tile 4o x 4d
        ull uacc[4][2] = {};
#pragma unroll 8
        for (int p = 0; p < 64; p++) {
            float4 av = *(const float4*)&sA[p * 68 + ty * 4];
            ulonglong2 bp2 = *(const ulonglong2*)&sB[p * 68 + tx * 4];
            ull a0 = pack2(av.x, av.x), a1 = pack2(av.y, av.y);
            ull a2 = pack2(av.z, av.z), a3 = pack2(av.w, av.w);
            ffma2(uacc[0][0], a0, bp2.x); ffma2(uacc[0][1], a0, bp2.y);
            ffma2(uacc[1][0], a1, bp2.x); ffma2(uacc[1][1], a1, bp2.y);
            ffma2(uacc[2][0], a2, bp2.x); ffma2(uacc[2][1], a2, bp2.y);
            ffma2(uacc[3][0], a3, bp2.x); ffma2(uacc[3][1], a3, bp2.y);
        }
        // write transposed: sUT[d][bb*64+o]
#pragma unroll
        for (int i = 0; i < 4; i++) {
            int o = ty * 4 + i;
#pragma unroll
            for (int j = 0; j < 2; j++) {
                float2 v = unpack2(uacc[i][j]);
                int d = tx * 4 + 2 * j;
                sUT[d * 132 + bb * 64 + o] = v.x;
                sUT[(d + 1) * 132 + bb * 64 + o] = v.y;
            }
        }
        __syncthreads();
    }

    // stage wout into sB (sync provided by first tile's stage barrier)
    for (int l = t; l < 2112; l += 256) sB[l] = wout[l];

    float zacc[8] = {0.f, 0.f, 0.f, 0.f, 0.f, 0.f, 0.f, 0.f};
    int r0 = ty * 8, e0 = tx * 4;

    for (int et = 0; et < 33; et++) {
        // stage G tile transposed: sA[d][e]
#pragma unroll
        for (int q = 0; q < 16; q++) {
            int l = t + q * 256;
            int e = l >> 6, d = l & 63;
            sA[d * 68 + e] = G[(size_t)(et * 64 + e) * 2112 + d];
        }
        __syncthreads();
        // y[r][e] = sum_d UT[d][r] * GT[d][e]; pairs over r (natural), broadcast e
        ull yacc[4][4] = {};
#pragma unroll 4
        for (int d = 0; d < 64; d++) {
            const float* put = &sUT[d * 132 + r0];
            ulonglong2 up0 = *(const ulonglong2*)(put);
            ulonglong2 up1 = *(const ulonglong2*)(put + 4);
            float4 gv = *(const float4*)&sA[d * 68 + e0];
            ull g0 = pack2(gv.x, gv.x), g1 = pack2(gv.y, gv.y);
            ull g2 = pack2(gv.z, gv.z), g3 = pack2(gv.w, gv.w);
            ffma2(yacc[0][0], up0.x, g0); ffma2(yacc[0][1], up0.x, g1);
            ffma2(yacc[0][2], up0.x, g2); ffma2(yacc[0][3], up0.x, g3);
            ffma2(yacc[1][0], up0.y, g0); ffma2(yacc[1][1], up0.y, g1);
            ffma2(yacc[1][2], up0.y, g2); ffma2(yacc[1][3], up0.y, g3);
            ffma2(yacc[2][0], up1.x, g0); ffma2(yacc[2][1], up1.x, g1);
            ffma2(yacc[2][2], up1.x, g2); ffma2(yacc[2][3], up1.x, g3);
            ffma2(yacc[3][0], up1.y, g0); ffma2(yacc[3][1], up1.y, g1);
            ffma2(yacc[3][2], up1.y, g2); ffma2(yacc[3][3], up1.y, g3);
        }
        __syncthreads();
        // epilogue: y += C; z += w * sigmoid(y)
#pragma unroll
        for (int rp = 0; rp < 4; rp++) {
            int rA = r0 + 2 * rp;
            int oA = rA & 63, oB = (rA + 1) & 63;
#pragma unroll
            for (int j = 0; j < 4; j++) {
                float2 y = unpack2(yacc[rp][j]);
                int e = et * 64 + e0 + j;
                float w = sB[e0 + j + et * 64];
                float ya = y.x + g_C[oA * 2112 + e];
                float yb = y.y + g_C[oB * 2112 + e];
                zacc[2 * rp]     += w * rcpf(1.f + __expf(-ya));
                zacc[2 * rp + 1] += w * rcpf(1.f + __expf(-yb));
            }
        }
    }

    __syncthreads();
    // cross-thread reduce over tx (reuse sA: 128 x 16)
#pragma unroll
    for (int i = 0; i < 8; i++) sA[(r0 + i) * 16 + tx] = zacc[i];
    __syncthreads();
    if (t < 128) {
        float z = 0.f;
#pragma unroll
        for (int q = 0; q < 16; q++) z += sA[t * 16 + q];
        z += outb[0];
        float a = pa[0];
        out[bpair * 128 + t] = z >= 0.f ? z : a * z;
    }
}

// ---------------- launcher ----------------
extern "C" void kernel_launch(void* const* d_in, const int* in_sizes, int n_in,
                              void* d_out, int out_size) {
    const float* x   = (const float*)d_in[0];
    const float* fiW = (const float*)d_in[1];
    const float* fib = (const float*)d_in[2];
    const float* f1W = (const float*)d_in[3];
    const float* f1b = (const float*)d_in[4];
    const float* o1W = (const float*)d_in[5];
    const float* o1b = (const float*)d_in[6];
    const float* cnW = (const float*)d_in[7];
    const float* cnb = (const float*)d_in[8];
    const float* caW = (const float*)d_in[9];
    const float* oaW = (const float*)d_in[10];
    const float* ntW = (const float*)d_in[11];
    const float* gW  = (const float*)d_in[12];
    const float* omW = (const float*)d_in[13];
    const float* omb = (const float*)d_in[14];
    const float* pa  = (const float*)d_in[15];
    const float* cm  = (const float*)d_in[16];
    float* out = (float*)d_out;

    void* p;
    cudaGetSymbolAddress(&p, g_h1);     float* ph1   = (float*)p;
    cudaGetSymbolAddress(&p, g_h2);     float* ph2   = (float*)p;
    cudaGetSymbolAddress(&p, g_hidden); float* phid  = (float*)p;
    cudaGetSymbolAddress(&p, g_att2);   float* patt2 = (float*)p;
    cudaGetSymbolAddress(&p, g_Cpart);  float* pCp   = (float*)p;

    cudaFuncSetAttribute(k_final, cudaFuncAttributeMaxDynamicSharedMemorySize, 68608);

    // batch-independent chain
    k_cfcfs<<<4096, 256>>>(cm, cnW, cnb, caW);
    k_csatt<<<64, 256>>>(oaW);
    k_att2<<<512, 256>>>(ntW);
    // C = att2 @ G[:,64:]^T   (split-K=8, deterministic reduce)
    sgemm_nt<<<dim3(33, 1, 8), 256>>>(patt2, gW, nullptr, pCp,
                                      2112, 2048, 2048, 2112, 64, 0, 64 * 2112);
    k_redC<<<528, 256>>>();

    // batch trunk
    sgemm_nt<<<dim3(16, 8, 1), 256>>>(x, fiW, fib, ph1, 1024, 2000, 2000, 2000, 0, 1, 0);
    sgemm_nt<<<dim3(2, 8, 1), 256>>>(ph1, f1W, f1b, ph2, 128, 1024, 1024, 1024, 0, 1, 0);
    sgemm_nt<<<dim3(64, 8, 1), 256>>>(ph2, o1W, o1b, phid, 4096, 128, 128, 128, 0, 1, 0);

    // fused final
    k_final<<<256, 256, 68608>>>(ntW, gW, omW, omb, pa, out);
}

// round 3
// speedup vs baseline: 1.9052x; 1.5521x over previous
#include <cuda_runtime.h>
#include <math.h>
#include <stdint.h>

// ---------------- scratch (static device globals; no allocation) ----------------
__device__ float g_h1[512 * 1024];
__device__ float g_h2[512 * 128];
__device__ float g_hidden[512 * 4096];      // [b][o*64+d]
__device__ float g_cfs[64 * 64 * 32];       // [x][y][h]
__device__ float g_csum[64 * 32];
__device__ float g_att[64 * 2048];          // [o][i*32+g]
__device__ float g_att2[64 * 2048];         // [o][j]
__device__ float g_Cpart[16 * 64 * 2112];
__device__ float g_C[64 * 2112];            // [o][e]
__device__ float g_GT[64 * 2112];           // [d][e] = G[e][d]

typedef unsigned long long ull;

__device__ __forceinline__ ull pack2(float x, float y) {
    ull r; asm("mov.b64 %0,{%1,%2};" : "=l"(r) : "f"(x), "f"(y)); return r;
}
__device__ __forceinline__ void ffma2(ull& d, ull a, ull b) {
    asm("fma.rn.f32x2 %0,%1,%2,%0;" : "+l"(d) : "l"(a), "l"(b));
}
__device__ __forceinline__ float2 unpack2(ull v) {
    float2 r; asm("mov.b64 {%0,%1},%2;" : "=f"(r.x), "=f"(r.y) : "l"(v)); return r;
}
__device__ __forceinline__ float eluf(float x) { return x > 0.f ? x : expm1f(x); }
__device__ __forceinline__ float rcpf(float x) {
    float r; asm("rcp.approx.f32 %0,%1;" : "=f"(r) : "f"(x)); return r;
}
__device__ __forceinline__ void cpasync16(uint32_t s, const void* g) {
    asm volatile("cp.async.ca.shared.global [%0], [%1], 16;" :: "r"(s), "l"(g));
}
__device__ __forceinline__ void cpcommit() { asm volatile("cp.async.commit_group;"); }
__device__ __forceinline__ void cpwait1() { asm volatile("cp.async.wait_group 1;"); }
__device__ __forceinline__ void cpwait0() { asm volatile("cp.async.wait_group 0;"); }

// ---------------- GT[d][e] = G[e][d] for d<64 ----------------------------------
__global__ __launch_bounds__(256) void k_gt(const float* __restrict__ G) {
    int d = blockIdx.y;
    int e = blockIdx.x * 256 + threadIdx.x;
    if (e < 2112) g_GT[d * 2112 + e] = G[(size_t)e * 2112 + d];
}

// ---------------- fused cf + cfs: 16 pairs per block ----------------------------
__global__ __launch_bounds__(256) void k_cfcfs(const float* __restrict__ cm,
                                               const float* __restrict__ cw,
                                               const float* __restrict__ cb,
                                               const float* __restrict__ caw) {
    __shared__ float cawT[8448];   // f*1056 + h*33 + g
    __shared__ float sc[256], red[256], sp[256], scm[128];
    int t = threadIdx.x;
    int f = t >> 5, g = t & 31;
#pragma unroll
    for (int q = 0; q < 32; q++) {
        int l = t + q * 256;
        int ff = l >> 10, r = l & 1023, gg = r >> 5, h = r & 31;
        cawT[ff * 1056 + h * 33 + gg] = caw[l];
    }
    if (t < 128) scm[t] = cm[blockIdx.x * 128 + t];
    float cwv = cw[t], cbv = cb[t];
    __syncthreads();
    for (int p = 0; p < 16; p++) {
        float m = scm[p * 8 + f];
        float v = eluf(fmaf(m, cwv, cbv));
        sc[t] = v;
        red[t] = expf(eluf(v));
        __syncthreads();
        for (int s = 128; s > 0; s >>= 1) {
            if (t < s) red[t] += red[t + s];
            __syncthreads();
        }
        float sden = red[0];
        float lin = 0.f;
#pragma unroll
        for (int h = 0; h < 32; h++) lin = fmaf(sc[f * 32 + h], cawT[f * 1056 + h * 33 + g], lin);
        float E = expf(eluf(v));
        sp[t] = eluf(E * lin / sden);
        __syncthreads();
        if (t < 32) {
            float sum = 0.f;
#pragma unroll
            for (int ff2 = 0; ff2 < 8; ff2++) sum += sp[ff2 * 32 + t];
            g_cfs[(blockIdx.x * 16 + p) * 32 + t] = eluf(sum * 0.125f);
        }
        __syncthreads();
    }
}

// ---------------- csum: block per x ---------------------------------------------
__global__ __launch_bounds__(256) void k_csum() {
    int x = blockIdx.x;
    int t = threadIdx.x;
    int ys = t >> 5, h = t & 31;
    float s = 0.f;
    for (int y = ys; y < 64; y += 8) s += expf(eluf(g_cfs[(x * 64 + y) * 32 + h]));
    __shared__ float r[256];
    r[t] = s;
    __syncthreads();
    if (t < 32) {
        float a = 0.f;
#pragma unroll
        for (int q = 0; q < 8; q++) a += r[q * 32 + t];
        g_csum[x * 32 + t] = a;
    }
}

// ---------------- att: block per i ----------------------------------------------
__global__ __launch_bounds__(256) void k_att(const float* __restrict__ oaw) {
    int i = blockIdx.x;
    int t = threadIdx.x;
    int osub = t >> 5, g = t & 31;
    __shared__ float sw[32 * 33];    // oawT[h*33+g]
    __shared__ float scf[64 * 32];   // cfs[o][h] at this i
#pragma unroll
    for (int q = 0; q < 4; q++) {
        int l = t + q * 256;
        int gg = l >> 5, h = l & 31;
        sw[h * 33 + gg] = oaw[i * 1024 + l];
    }
#pragma unroll
    for (int q = 0; q < 8; q++) {
        int l = t + q * 256;
        int o = l >> 5, h = l & 31;
        scf[l] = g_cfs[(o * 64 + i) * 32 + h];
    }
    __syncthreads();
#pragma unroll
    for (int oq = 0; oq < 8; oq++) {
        int o = oq * 8 + osub;
        float lin = 0.f;
#pragma unroll
        for (int h = 0; h < 32; h++) lin = fmaf(scf[o * 32 + h], sw[h * 33 + g], lin);
        float E = expf(eluf(scf[o * 32 + g]));
        g_att[o * 2048 + i * 32 + g] = E / g_csum[o * 32 + g] * lin;
    }
}

// att2[o,j] = sum_p Wnt[o,p] * att[p,j]
__global__ __launch_bounds__(256) void k_att2(const float* __restrict__ wnt) {
    int idx = blockIdx.x * 256 + threadIdx.x;   // 131072
    int o = idx >> 11, j = idx & 2047;
    float acc = 0.f;
#pragma unroll 8
    for (int p = 0; p < 64; p++) acc += wnt[o * 64 + p] * g_att[p * 2048 + j];
    g_att2[o * 2048 + j] = acc;
}

// deterministic split-K reduce for C
__global__ void k_redC() {
    int i = blockIdx.x * 256 + threadIdx.x;     // 135168
    float s = 0.f;
#pragma unroll
    for (int z = 0; z < 16; z++) s += g_Cpart[z * 135168 + i];
    g_C[i] = s;
}

// ---------------- generic NT sgemm, double-buffered, f32x2 ----------------------
// C = act(A[M,K] * B[N,K]^T + bias); 64x64 tile, 256 threads, 4x4 per thread.
__global__ __launch_bounds__(256) void sgemm_nt(
    const float* __restrict__ A, const float* __restrict__ B,
    const float* __restrict__ bias, float* __restrict__ C,
    int N, int K, int lda, int ldb, int koffB, int relu, int zstride) {
    __shared__ __align__(16) float As[2][16 * 68];
    __shared__ __align__(16) float Bs[2][16 * 68];
    int t = threadIdx.x;
    int tx = t & 15, ty = t >> 4;
    int row0 = blockIdx.y * 64, col0 = blockIdx.x * 64;
    int kPer = K / gridDim.z;
    int k0 = blockIdx.z * kPer;
    const float* Ap = A + (size_t)(row0 + ty) * lda + k0 + tx;
    const float* Bp = B + (size_t)(col0 + ty) * ldb + koffB + k0 + tx;
    float ra[4], rb[4];
#pragma unroll
    for (int q = 0; q < 4; q++) {
        ra[q] = Ap[(size_t)q * 16 * lda];
        rb[q] = Bp[(size_t)q * 16 * ldb];
    }
#pragma unroll
    for (int q = 0; q < 4; q++) {
        As[0][tx * 68 + ty + q * 16] = ra[q];
        Bs[0][tx * 68 + ty + q * 16] = rb[q];
    }
    __syncthreads();
    ull acc[4][2] = {};
    int buf = 0;
    for (int kb = 16; kb <= kPer; kb += 16) {
        if (kb < kPer) {
#pragma unroll
            for (int q = 0; q < 4; q++) {
                ra[q] = Ap[kb + (size_t)q * 16 * lda];
                rb[q] = Bp[kb + (size_t)q * 16 * ldb];
            }
        }
#pragma unroll
        for (int kk = 0; kk < 16; kk++) {
            float4 av = *(const float4*)&As[buf][kk * 68 + ty * 4];
            ulonglong2 bp = *(const ulonglong2*)&Bs[buf][kk * 68 + tx * 4];
            ull a0 = pack2(av.x, av.x), a1 = pack2(av.y, av.y);
            ull a2 = pack2(av.z, av.z), a3 = pack2(av.w, av.w);
            ffma2(acc[0][0], a0, bp.x); ffma2(acc[0][1], a0, bp.y);
            ffma2(acc[1][0], a1, bp.x); ffma2(acc[1][1], a1, bp.y);
            ffma2(acc[2][0], a2, bp.x); ffma2(acc[2][1], a2, bp.y);
            ffma2(acc[3][0], a3, bp.x); ffma2(acc[3][1], a3, bp.y);
        }
        if (kb < kPer) {
#pragma unroll
            for (int q = 0; q < 4; q++) {
                As[buf ^ 1][tx * 68 + ty + q * 16] = ra[q];
                Bs[buf ^ 1][tx * 68 + ty + q * 16] = rb[q];
            }
            __syncthreads();
            buf ^= 1;
        }
    }
#pragma unroll
    for (int i = 0; i < 4; i++) {
        int m = row0 + ty * 4 + i;
#pragma unroll
        for (int j = 0; j < 2; j++) {
            float2 v = unpack2(acc[i][j]);
            int n = col0 + tx * 4 + 2 * j;
            if (bias) { v.x += bias[n]; v.y += bias[n + 1]; }
            if (relu) { v.x = fmaxf(v.x, 0.f); v.y = fmaxf(v.y, 0.f); }
            float* dst = C + (size_t)zstride * blockIdx.z + (size_t)m * N + n;
            dst[0] = v.x;
            dst[1] = v.y;
        }
    }
}

// ---------------- fused final: U + y GEMM + sigmoid + weighted reduce ----------
// block = 2 batches (grid 256). smem: sUT[64d][132], sA0/sA1 (G tiles, 64*68),
// sB (hidden / wout).
__global__ __launch_bounds__(256) void k_final(
    const float* __restrict__ Wnt, const float* __restrict__ GT,
    const float* __restrict__ wout, const float* __restrict__ outb,
    const float* __restrict__ pa, float* __restrict__ out) {
    extern __shared__ __align__(16) float smem[];
    float* sUT = smem;                 // 8448
    float* sA0 = smem + 8448;          // 4352
    float* sA1 = smem + 12800;         // 4352
    float* sB  = smem + 17152;         // 4352
    int t = threadIdx.x;
    int tx = t & 15, ty = t >> 4;
    int bpair = blockIdx.x;
    uint32_t sA1u = (uint32_t)__cvta_generic_to_shared(sA1);
    uint32_t sA0u = (uint32_t)__cvta_generic_to_shared(sA0);

    // prefetch G tile 0 -> sA1 (cp.async, 4 x 16B per thread)
#pragma unroll
    for (int q = 0; q < 4; q++) {
        int u = t + q * 256;               // 1024 float4 units
        int d = u >> 4, e4 = u & 15;
        cpasync16(sA1u + (d * 68 + e4 * 4) * 4, GT + (size_t)d * 2112 + e4 * 4);
    }
    cpcommit();

    // stage Wnt transposed: sA0[p][o]
#pragma unroll
    for (int q = 0; q < 16; q++) {
        int l = t + q * 256;
        int o = l >> 6, p = l & 63;
        sA0[p * 68 + o] = Wnt[l];
    }

    for (int bb = 0; bb < 2; bb++) {
        const float4* hid = (const float4*)(g_hidden + (size_t)(2 * bpair + bb) * 4096);
#pragma unroll
        for (int q = 0; q < 4; q++) {
            int l4 = t + q * 256;
            int p = l4 >> 4, d = (l4 & 15) * 4;
            *(float4*)&sB[p * 68 + d] = hid[l4];
        }
        __syncthreads();
        ull uacc[4][2] = {};
#pragma unroll 8
        for (int p = 0; p < 64; p++) {
            float4 av = *(const float4*)&sA0[p * 68 + ty * 4];
            ulonglong2 bp2 = *(const ulonglong2*)&sB[p * 68 + tx * 4];
            ull a0 = pack2(av.x, av.x), a1 = pack2(av.y, av.y);
            ull a2 = pack2(av.z, av.z), a3 = pack2(av.w, av.w);
            ffma2(uacc[0][0], a0, bp2.x); ffma2(uacc[0][1], a0, bp2.y);
            ffma2(uacc[1][0], a1, bp2.x); ffma2(uacc[1][1], a1, bp2.y);
            ffma2(uacc[2][0], a2, bp2.x); ffma2(uacc[2][1], a2, bp2.y);
            ffma2(uacc[3][0], a3, bp2.x); ffma2(uacc[3][1], a3, bp2.y);
        }
        // write transposed: sUT[d][bb*64+o]
#pragma unroll
        for (int i = 0; i < 4; i++) {
            int o = ty * 4 + i;
#pragma unroll
            for (int j = 0; j < 2; j++) {
                float2 v = unpack2(uacc[i][j]);
                int d = tx * 4 + 2 * j;
                sUT[d * 132 + bb * 64 + o] = v.x;
                sUT[(d + 1) * 132 + bb * 64 + o] = v.y;
            }
        }
        __syncthreads();
    }

    // stage wout into sB
    for (int l = t; l < 2112; l += 256) sB[l] = wout[l];

    float zacc[8] = {0.f, 0.f, 0.f, 0.f, 0.f, 0.f, 0.f, 0.f};
    int r0 = ty * 8, e0 = tx * 4;

    for (int et = 0; et < 33; et++) {
        float* gbuf = (et & 1) ? sA0 : sA1;
        if (et < 32) {
            uint32_t dstu = (et & 1) ? sA1u : sA0u;
            const float* src = GT + (et + 1) * 64;
#pragma unroll
            for (int q = 0; q < 4; q++) {
                int u = t + q * 256;
                int d = u >> 4, e4 = u & 15;
                cpasync16(dstu + (d * 68 + e4 * 4) * 4, src + (size_t)d * 2112 + e4 * 4);
            }
            cpcommit();
            cpwait1();
        } else {
            cpwait0();
        }
        __syncthreads();
        ull yacc[4][4] = {};
#pragma unroll 4
        for (int d = 0; d < 64; d++) {
            const float* put = &sUT[d * 132 + r0];
            ulonglong2 up0 = *(const ulonglong2*)(put);
            ulonglong2 up1 = *(const ulonglong2*)(put + 4);
            float4 gv = *(const float4*)&gbuf[d * 68 + e0];
            ull g0 = pack2(gv.x, gv.x), g1 = pack2(gv.y, gv.y);
            ull g2 = pack2(gv.z, gv.z), g3 = pack2(gv.w, gv.w);
            ffma2(yacc[0][0], up0.x, g0); ffma2(yacc[0][1], up0.x, g1);
            ffma2(yacc[0][2], up0.x, g2); ffma2(yacc[0][3], up0.x, g3);
            ffma2(yacc[1][0], up0.y, g0); ffma2(yacc[1][1], up0.y, g1);
            ffma2(yacc[1][2], up0.y, g2); ffma2(yacc[1][3], up0.y, g3);
            ffma2(yacc[2][0], up1.x, g0); ffma2(yacc[2][1], up1.x, g1);
            ffma2(yacc[2][2], up1.x, g2); ffma2(yacc[2][3], up1.x, g3);
            ffma2(yacc[3][0], up1.y, g0); ffma2(yacc[3][1], up1.y, g1);
            ffma2(yacc[3][2], up1.y, g2); ffma2(yacc[3][3], up1.y, g3);
        }
#pragma unroll
        for (int rp = 0; rp < 4; rp++) {
            int rA = r0 + 2 * rp;
            int oA = rA & 63, oB = (rA + 1) & 63;
#pragma unroll
            for (int j = 0; j < 4; j++) {
                float2 y = unpack2(yacc[rp][j]);
                int e = et * 64 + e0 + j;
                float w = sB[e];
                float ya = y.x + g_C[oA * 2112 + e];
                float yb = y.y + g_C[oB * 2112 + e];
                zacc[2 * rp]     += w * rcpf(1.f + __expf(-ya));
                zacc[2 * rp + 1] += w * rcpf(1.f + __expf(-yb));
            }
        }
        __syncthreads();
    }

    // cross-thread reduce over tx (reuse sA0 region: 128 x 16)
#pragma unroll
    for (int i = 0; i < 8; i++) sA0[(r0 + i) * 16 + tx] = zacc[i];
    __syncthreads();
    if (t < 128) {
        float z = 0.f;
#pragma unroll
        for (int q = 0; q < 16; q++) z += sA0[t * 16 + q];
        z += outb[0];
        float a = pa[0];
        out[bpair * 128 + t] = z >= 0.f ? z : a * z;
    }
}

// ---------------- launcher ----------------
extern "C" void kernel_launch(void* const* d_in, const int* in_sizes, int n_in,
                              void* d_out, int out_size) {
    const float* x   = (const float*)d_in[0];
    const float* fiW = (const float*)d_in[1];
    const float* fib = (const float*)d_in[2];
    const float* f1W = (const float*)d_in[3];
    const float* f1b = (const float*)d_in[4];
    const float* o1W = (const float*)d_in[5];
    const float* o1b = (const float*)d_in[6];
    const float* cnW = (const float*)d_in[7];
    const float* cnb = (const float*)d_in[8];
    const float* caW = (const float*)d_in[9];
    const float* oaW = (const float*)d_in[10];
    const float* ntW = (const float*)d_in[11];
    const float* gW  = (const float*)d_in[12];
    const float* omW = (const float*)d_in[13];
    const float* omb = (const float*)d_in[14];
    const float* pa  = (const float*)d_in[15];
    const float* cm  = (const float*)d_in[16];
    float* out = (float*)d_out;

    void* p;
    cudaGetSymbolAddress(&p, g_h1);     float* ph1   = (float*)p;
    cudaGetSymbolAddress(&p, g_h2);     float* ph2   = (float*)p;
    cudaGetSymbolAddress(&p, g_hidden); float* phid  = (float*)p;
    cudaGetSymbolAddress(&p, g_att2);   float* patt2 = (float*)p;
    cudaGetSymbolAddress(&p, g_Cpart);  float* pCp   = (float*)p;
    cudaGetSymbolAddress(&p, g_GT);     float* pGT   = (float*)p;

    cudaFuncSetAttribute(k_final, cudaFuncAttributeMaxDynamicSharedMemorySize, 86016);

    // batch-independent chain
    k_gt<<<dim3(9, 64), 256>>>(gW);
    k_cfcfs<<<256, 256>>>(cm, cnW, cnb, caW);
    k_csum<<<64, 256>>>();
    k_att<<<64, 256>>>(oaW);
    k_att2<<<512, 256>>>(ntW);
    // C = att2 @ G[:,64:]^T   (split-K=16, deterministic reduce)
    sgemm_nt<<<dim3(33, 1, 16), 256>>>(patt2, gW, nullptr, pCp,
                                       2112, 2048, 2048, 2112, 64, 0, 64 * 2112);
    k_redC<<<528, 256>>>();

    // batch trunk
    sgemm_nt<<<dim3(16, 8, 1), 256>>>(x, fiW, fib, ph1, 1024, 2000, 2000, 2000, 0, 1, 0);
    sgemm_nt<<<dim3(2, 8, 1), 256>>>(ph1, f1W, f1b, ph2, 128, 1024, 1024, 1024, 0, 1, 0);
    sgemm_nt<<<dim3(64, 8, 1), 256>>>(ph2, o1W, o1b, phid, 4096, 128, 128, 128, 0, 1, 0);

    // fused final
    k_final<<<256, 256, 86016>>>(ntW, pGT, omW, omb, pa, out);
}

// round 4
// speedup vs baseline: 2.1314x; 1.1187x over previous
#include <cuda_runtime.h>
#include <math.h>
#include <stdint.h>

// ---------------- scratch (static device globals; no allocation) ----------------
__device__ float g_h1[512 * 1024];
__device__ float g_h2[512 * 128];
__device__ float g_h2p[8 * 512 * 128];
__device__ float g_hidden[512 * 4096];      // [b][o*64+d]
__device__ float g_cfs[64 * 64 * 32];       // [x][y][h]
__device__ float g_csum[64 * 32];
__device__ float g_att[64 * 2048];          // [o][i*32+g]
__device__ float g_att2[64 * 2048];         // [o][j]
__device__ float g_Cpart[16 * 64 * 2112];
__device__ float g_C[64 * 2112];            // [o][e]
__device__ float g_GT[64 * 2112];           // [d][e] = G[e][d]

typedef unsigned long long ull;

__device__ __forceinline__ ull pack2(float x, float y) {
    ull r; asm("mov.b64 %0,{%1,%2};" : "=l"(r) : "f"(x), "f"(y)); return r;
}
__device__ __forceinline__ void ffma2(ull& d, ull a, ull b) {
    asm("fma.rn.f32x2 %0,%1,%2,%0;" : "+l"(d) : "l"(a), "l"(b));
}
__device__ __forceinline__ float2 unpack2(ull v) {
    float2 r; asm("mov.b64 {%0,%1},%2;" : "=f"(r.x), "=f"(r.y) : "l"(v)); return r;
}
__device__ __forceinline__ float eluf(float x) { return x > 0.f ? x : expm1f(x); }
__device__ __forceinline__ float rcpf(float x) {
    float r; asm("rcp.approx.f32 %0,%1;" : "=f"(r) : "f"(x)); return r;
}
__device__ __forceinline__ void cpasync16(uint32_t s, const void* g) {
    asm volatile("cp.async.ca.shared.global [%0], [%1], 16;" :: "r"(s), "l"(g));
}
__device__ __forceinline__ void cpcommit() { asm volatile("cp.async.commit_group;"); }
__device__ __forceinline__ void cpwait0() { asm volatile("cp.async.wait_group 0;"); }

// ---------------- GT[d][e] = G[e][d] for d<64 ----------------------------------
__global__ __launch_bounds__(256) void k_gt(const float* __restrict__ G) {
    int d = blockIdx.y;
    int e = blockIdx.x * 256 + threadIdx.x;
    if (e < 2112) g_GT[d * 2112 + e] = G[(size_t)e * 2112 + d];
}

// ---------------- fused cf + cfs: 16 pairs per block ----------------------------
__global__ __launch_bounds__(256) void k_cfcfs(const float* __restrict__ cm,
                                               const float* __restrict__ cw,
                                               const float* __restrict__ cb,
                                               const float* __restrict__ caw) {
    __shared__ float cawT[8448];   // f*1056 + h*33 + g
    __shared__ float sc[256], red[8], sp[256], scm[128];
    int t = threadIdx.x;
    int f = t >> 5, g = t & 31;
#pragma unroll
    for (int q = 0; q < 32; q++) {
        int l = t + q * 256;
        int ff = l >> 10, r = l & 1023, gg = r >> 5, h = r & 31;
        cawT[ff * 1056 + h * 33 + gg] = caw[l];
    }
    if (t < 128) scm[t] = cm[blockIdx.x * 128 + t];
    float cwv = cw[t], cbv = cb[t];
    __syncthreads();
    for (int p = 0; p < 16; p++) {
        float m = scm[p * 8 + f];
        float v = eluf(fmaf(m, cwv, cbv));
        sc[t] = v;
        float r = expf(eluf(v));
#pragma unroll
        for (int off = 16; off; off >>= 1) r += __shfl_xor_sync(0xffffffffu, r, off);
        if (g == 0) red[f] = r;
        __syncthreads();
        float sden = 0.f;
#pragma unroll
        for (int q = 0; q < 8; q++) sden += red[q];
        float lin = 0.f;
#pragma unroll
        for (int h = 0; h < 32; h++) lin = fmaf(sc[f * 32 + h], cawT[f * 1056 + h * 33 + g], lin);
        float E = expf(eluf(v));
        sp[t] = eluf(E * lin / sden);
        __syncthreads();
        if (t < 32) {
            float sum = 0.f;
#pragma unroll
            for (int ff2 = 0; ff2 < 8; ff2++) sum += sp[ff2 * 32 + t];
            g_cfs[(blockIdx.x * 16 + p) * 32 + t] = eluf(sum * 0.125f);
        }
        __syncthreads();
    }
}

// ---------------- csum: block per x ---------------------------------------------
__global__ __launch_bounds__(256) void k_csum() {
    int x = blockIdx.x;
    int t = threadIdx.x;
    int ys = t >> 5, h = t & 31;
    float s = 0.f;
    for (int y = ys; y < 64; y += 8) s += expf(eluf(g_cfs[(x * 64 + y) * 32 + h]));
    __shared__ float r[256];
    r[t] = s;
    __syncthreads();
    if (t < 32) {
        float a = 0.f;
#pragma unroll
        for (int q = 0; q < 8; q++) a += r[q * 32 + t];
        g_csum[x * 32 + t] = a;
    }
}

// ---------------- att: block per (i, o-group of 16) -----------------------------
__global__ __launch_bounds__(256) void k_att(const float* __restrict__ oaw) {
    int bx = blockIdx.x;
    int i = bx >> 2, og = bx & 3;
    int t = threadIdx.x;
    int osub = t >> 5, g = t & 31;
    __shared__ float sw[32 * 33];    // oawT[h*33+g]
    __shared__ float scf[16 * 32];   // cfs[o'][h] at this i
#pragma unroll
    for (int q = 0; q < 4; q++) {
        int l = t + q * 256;
        int gg = l >> 5, h = l & 31;
        sw[h * 33 + gg] = oaw[i * 1024 + l];
    }
#pragma unroll
    for (int q = 0; q < 2; q++) {
        int l = t + q * 256;
        int op = l >> 5, h = l & 31;
        scf[l] = g_cfs[((og * 16 + op) * 64 + i) * 32 + h];
    }
    __syncthreads();
#pragma unroll
    for (int q = 0; q < 2; q++) {
        int op = osub * 2 + q;
        int o = og * 16 + op;
        float lin = 0.f;
#pragma unroll
        for (int h = 0; h < 32; h++) lin = fmaf(scf[op * 32 + h], sw[h * 33 + g], lin);
        float E = expf(eluf(scf[op * 32 + g]));
        g_att[o * 2048 + i * 32 + g] = E / g_csum[o * 32 + g] * lin;
    }
}

// att2[o,j] = sum_p Wnt[o,p] * att[p,j]
__global__ __launch_bounds__(256) void k_att2(const float* __restrict__ wnt) {
    int idx = blockIdx.x * 256 + threadIdx.x;   // 131072
    int o = idx >> 11, j = idx & 2047;
    float acc = 0.f;
#pragma unroll 8
    for (int p = 0; p < 64; p++) acc += wnt[o * 64 + p] * g_att[p * 2048 + j];
    g_att2[o * 2048 + j] = acc;
}

// deterministic split-K reduce for C
__global__ void k_redC() {
    int i = blockIdx.x * 256 + threadIdx.x;     // 135168
    float s = 0.f;
#pragma unroll
    for (int z = 0; z < 16; z++) s += g_Cpart[z * 135168 + i];
    g_C[i] = s;
}

// deterministic split-K reduce for h2 (+bias+relu)
__global__ void k_redH(const float* __restrict__ f1b) {
    int idx = blockIdx.x * 256 + threadIdx.x;   // 65536
    float s = 0.f;
#pragma unroll
    for (int z = 0; z < 8; z++) s += g_h2p[z * 65536 + idx];
    g_h2[idx] = fmaxf(s + f1b[idx & 127], 0.f);
}

// ---------------- generic NT sgemm, double-buffered, f32x2 ----------------------
// C = act(A[M,K] * B[N,K]^T + bias); 64x64 tile, 256 threads, 4x4 per thread.
__global__ __launch_bounds__(256) void sgemm_nt(
    const float* __restrict__ A, const float* __restrict__ B,
    const float* __restrict__ bias, float* __restrict__ C,
    int N, int K, int lda, int ldb, int koffB, int relu, int zstride) {
    __shared__ __align__(16) float As[2][16 * 68];
    __shared__ __align__(16) float Bs[2][16 * 68];
    int t = threadIdx.x;
    int tx = t & 15, ty = t >> 4;
    int row0 = blockIdx.y * 64, col0 = blockIdx.x * 64;
    int kPer = K / gridDim.z;
    int k0 = blockIdx.z * kPer;
    const float* Ap = A + (size_t)(row0 + ty) * lda + k0 + tx;
    const float* Bp = B + (size_t)(col0 + ty) * ldb + koffB + k0 + tx;
    float ra[4], rb[4];
#pragma unroll
    for (int q = 0; q < 4; q++) {
        ra[q] = Ap[(size_t)q * 16 * lda];
        rb[q] = Bp[(size_t)q * 16 * ldb];
    }
#pragma unroll
    for (int q = 0; q < 4; q++) {
        As[0][tx * 68 + ty + q * 16] = ra[q];
        Bs[0][tx * 68 + ty + q * 16] = rb[q];
    }
    __syncthreads();
    ull acc[4][2] = {};
    int buf = 0;
    for (int kb = 16; kb <= kPer; kb += 16) {
        if (kb < kPer) {
#pragma unroll
            for (int q = 0; q < 4; q++) {
                ra[q] = Ap[kb + (size_t)q * 16 * lda];
                rb[q] = Bp[kb + (size_t)q * 16 * ldb];
            }
        }
#pragma unroll
        for (int kk = 0; kk < 16; kk++) {
            float4 av = *(const float4*)&As[buf][kk * 68 + ty * 4];
            ulonglong2 bp = *(const ulonglong2*)&Bs[buf][kk * 68 + tx * 4];
            ull a0 = pack2(av.x, av.x), a1 = pack2(av.y, av.y);
            ull a2 = pack2(av.z, av.z), a3 = pack2(av.w, av.w);
            ffma2(acc[0][0], a0, bp.x); ffma2(acc[0][1], a0, bp.y);
            ffma2(acc[1][0], a1, bp.x); ffma2(acc[1][1], a1, bp.y);
            ffma2(acc[2][0], a2, bp.x); ffma2(acc[2][1], a2, bp.y);
            ffma2(acc[3][0], a3, bp.x); ffma2(acc[3][1], a3, bp.y);
        }
        if (kb < kPer) {
#pragma unroll
            for (int q = 0; q < 4; q++) {
                As[buf ^ 1][tx * 68 + ty + q * 16] = ra[q];
                Bs[buf ^ 1][tx * 68 + ty + q * 16] = rb[q];
            }
            __syncthreads();
            buf ^= 1;
        }
    }
#pragma unroll
    for (int i = 0; i < 4; i++) {
        int m = row0 + ty * 4 + i;
#pragma unroll
        for (int j = 0; j < 2; j++) {
            float2 v = unpack2(acc[i][j]);
            int n = col0 + tx * 4 + 2 * j;
            if (bias) { v.x += bias[n]; v.y += bias[n + 1]; }
            if (relu) { v.x = fmaxf(v.x, 0.f); v.y = fmaxf(v.y, 0.f); }
            float* dst = C + (size_t)zstride * blockIdx.z + (size_t)m * N + n;
            dst[0] = v.x;
            dst[1] = v.y;
        }
    }
}

// ---------------- fused final: U + y GEMM + sigmoid + weighted reduce ----------
// block = 2 batches (grid 256). Dynamic smem (floats):
//   sUT[8448] sA0[4352] sA1[4352] sB[2112] sC0[4352] sC1[4352]  = 111872 B
// G tile and C tile both streamed via cp.async, one commit group per tile.
__global__ __launch_bounds__(256) void k_final(
    const float* __restrict__ Wnt, const float* __restrict__ GT,
    const float* __restrict__ Cg, const float* __restrict__ wout,
    const float* __restrict__ outb, const float* __restrict__ pa,
    float* __restrict__ out) {
    extern __shared__ __align__(16) float smem[];
    float* sUT = smem;               // 8448
    float* sA0 = sUT + 8448;         // 4352
    float* sA1 = sA0 + 4352;         // 4352
    float* sB  = sA1 + 4352;         // 2112
    float* sC0 = sB + 2112;          // 4352
    float* sC1 = sC0 + 4352;         // 4352
    int t = threadIdx.x;
    int tx = t & 15, ty = t >> 4;
    int bpair = blockIdx.x;
    uint32_t sA0u = (uint32_t)__cvta_generic_to_shared(sA0);
    uint32_t sA1u = (uint32_t)__cvta_generic_to_shared(sA1);
    uint32_t sC0u = (uint32_t)__cvta_generic_to_shared(sC0);
    uint32_t sC1u = (uint32_t)__cvta_generic_to_shared(sC1);

    // prefetch G tile 0 -> sA1 (overlaps the whole U phase)
#pragma unroll
    for (int q = 0; q < 4; q++) {
        int u = t + q * 256;
        int d = u >> 4, e4 = u & 15;
        cpasync16(sA1u + (d * 68 + e4 * 4) * 4, GT + (size_t)d * 2112 + e4 * 4);
    }
    cpcommit();

    // stage Wnt transposed: sA0[p][o]
#pragma unroll
    for (int q = 0; q < 16; q++) {
        int l = t + q * 256;
        int o = l >> 6, p = l & 63;
        sA0[p * 68 + o] = Wnt[l];
    }

    for (int bb = 0; bb < 2; bb++) {
        const float4* hid = (const float4*)(g_hidden + (size_t)(2 * bpair + bb) * 4096);
#pragma unroll
        for (int q = 0; q < 4; q++) {
            int l4 = t + q * 256;
            int p = l4 >> 4, d = (l4 & 15) * 4;
            *(float4*)&sC0[p * 68 + d] = hid[l4];
        }
        __syncthreads();
        ull uacc[4][2] = {};
#pragma unroll 8
        for (int p = 0; p < 64; p++) {
            float4 av = *(const float4*)&sA0[p * 68 + ty * 4];
            ulonglong2 bp2 = *(const ulonglong2*)&sC0[p * 68 + tx * 4];
            ull a0 = pack2(av.x, av.x), a1 = pack2(av.y, av.y);
            ull a2 = pack2(av.z, av.z), a3 = pack2(av.w, av.w);
            ffma2(uacc[0][0], a0, bp2.x); ffma2(uacc[0][1], a0, bp2.y);
            ffma2(uacc[1][0], a1, bp2.x); ffma2(uacc[1][1], a1, bp2.y);
            ffma2(uacc[2][0], a2, bp2.x); ffma2(uacc[2][1], a2, bp2.y);
            ffma2(uacc[3][0], a3, bp2.x); ffma2(uacc[3][1], a3, bp2.y);
        }
        // write transposed: sUT[d][bb*64+o]
#pragma unroll
        for (int i = 0; i < 4; i++) {
            int o = ty * 4 + i;
#pragma unroll
            for (int j = 0; j < 2; j++) {
                float2 v = unpack2(uacc[i][j]);
                int d = tx * 4 + 2 * j;
                sUT[d * 132 + bb * 64 + o] = v.x;
                sUT[(d + 1) * 132 + bb * 64 + o] = v.y;
            }
        }
        __syncthreads();
    }

    // sC0 free now: prefetch C tile 0
#pragma unroll
    for (int q = 0; q < 4; q++) {
        int u = t + q * 256;
        int o = u >> 4, e4 = u & 15;
        cpasync16(sC0u + (o * 68 + e4 * 4) * 4, Cg + (size_t)o * 2112 + e4 * 4);
    }
    cpcommit();

    // stage wout
    for (int l = t; l < 2112; l += 256) sB[l] = wout[l];

    float zacc[8] = {0.f, 0.f, 0.f, 0.f, 0.f, 0.f, 0.f, 0.f};
    int r0 = ty * 8, e0 = tx * 4;

    for (int et = 0; et < 33; et++) {
        cpwait0();
        __syncthreads();
        float* gbuf = (et & 1) ? sA0 : sA1;
        float* cbuf = (et & 1) ? sC1 : sC0;
        if (et < 32) {
            uint32_t gd = (et & 1) ? sA1u : sA0u;
            uint32_t cd = (et & 1) ? sC0u : sC1u;
            const float* gsrc = GT + (et + 1) * 64;
            const float* csrc = Cg + (et + 1) * 64;
#pragma unroll
            for (int q = 0; q < 4; q++) {
                int u = t + q * 256;
                int r = u >> 4, e4 = u & 15;
                cpasync16(gd + (r * 68 + e4 * 4) * 4, gsrc + (size_t)r * 2112 + e4 * 4);
                cpasync16(cd + (r * 68 + e4 * 4) * 4, csrc + (size_t)r * 2112 + e4 * 4);
            }
            cpcommit();
        }
        ull yacc[4][4] = {};
#pragma unroll 4
        for (int d = 0; d < 64; d++) {
            const float* put = &sUT[d * 132 + r0];
            ulonglong2 up0 = *(const ulonglong2*)(put);
            ulonglong2 up1 = *(const ulonglong2*)(put + 4);
            float4 gv = *(const float4*)&gbuf[d * 68 + e0];
            ull g0 = pack2(gv.x, gv.x), g1 = pack2(gv.y, gv.y);
            ull g2 = pack2(gv.z, gv.z), g3 = pack2(gv.w, gv.w);
            ffma2(yacc[0][0], up0.x, g0); ffma2(yacc[0][1], up0.x, g1);
            ffma2(yacc[0][2], up0.x, g2); ffma2(yacc[0][3], up0.x, g3);
            ffma2(yacc[1][0], up0.y, g0); ffma2(yacc[1][1], up0.y, g1);
            ffma2(yacc[1][2], up0.y, g2); ffma2(yacc[1][3], up0.y, g3);
            ffma2(yacc[2][0], up1.x, g0); ffma2(yacc[2][1], up1.x, g1);
            ffma2(yacc[2][2], up1.x, g2); ffma2(yacc[2][3], up1.x, g3);
            ffma2(yacc[3][0], up1.y, g0); ffma2(yacc[3][1], up1.y, g1);
            ffma2(yacc[3][2], up1.y, g2); ffma2(yacc[3][3], up1.y, g3);
        }
        // epilogue: y += C (from smem); z += w * sigmoid(y)
        float4 wv = *(const float4*)&sB[et * 64 + e0];
        float wj[4] = {wv.x, wv.y, wv.z, wv.w};
#pragma unroll
        for (int rp = 0; rp < 4; rp++) {
            int rA = r0 + 2 * rp;
            int oA = rA & 63, oB = (rA + 1) & 63;
            float4 cA = *(const float4*)&cbuf[oA * 68 + e0];
            float4 cB = *(const float4*)&cbuf[oB * 68 + e0];
            float cAj[4] = {cA.x, cA.y, cA.z, cA.w};
            float cBj[4] = {cB.x, cB.y, cB.z, cB.w};
#pragma unroll
            for (int j = 0; j < 4; j++) {
                float2 y = unpack2(yacc[rp][j]);
                float ya = y.x + cAj[j];
                float yb = y.y + cBj[j];
                zacc[2 * rp]     += wj[j] * rcpf(1.f + __expf(-ya));
                zacc[2 * rp + 1] += wj[j] * rcpf(1.f + __expf(-yb));
            }
        }
    }

    __syncthreads();
    // cross-thread reduce over tx (reuse sA0 region: 128 x 16)
#pragma unroll
    for (int i = 0; i < 8; i++) sA0[(r0 + i) * 16 + tx] = zacc[i];
    __syncthreads();
    if (t < 128) {
        float z = 0.f;
#pragma unroll
        for (int q = 0; q < 16; q++) z += sA0[t * 16 + q];
        z += outb[0];
        float a = pa[0];
        out[bpair * 128 + t] = z >= 0.f ? z : a * z;
    }
}

// ---------------- launcher ----------------
extern "C" void kernel_launch(void* const* d_in, const int* in_sizes, int n_in,
                              void* d_out, int out_size) {
    const float* x   = (const float*)d_in[0];
    const float* fiW = (const float*)d_in[1];
    const float* fib = (const float*)d_in[2];
    const float* f1W = (const float*)d_in[3];
    const float* f1b = (const float*)d_in[4];
    const float* o1W = (const float*)d_in[5];
    const float* o1b = (const float*)d_in[6];
    const float* cnW = (const float*)d_in[7];
    const float* cnb = (const float*)d_in[8];
    const float* caW = (const float*)d_in[9];
    const float* oaW = (const float*)d_in[10];
    const float* ntW = (const float*)d_in[11];
    const float* gW  = (const float*)d_in[12];
    const float* omW = (const float*)d_in[13];
    const float* omb = (const float*)d_in[14];
    const float* pa  = (const float*)d_in[15];
    const float* cm  = (const float*)d_in[16];
    float* out = (float*)d_out;

    void* p;
    cudaGetSymbolAddress(&p, g_h1);     float* ph1   = (float*)p;
    cudaGetSymbolAddress(&p, g_h2);     float* ph2   = (float*)p;
    cudaGetSymbolAddress(&p, g_h2p);    float* ph2p  = (float*)p;
    cudaGetSymbolAddress(&p, g_hidden); float* phid  = (float*)p;
    cudaGetSymbolAddress(&p, g_att2);   float* patt2 = (float*)p;
    cudaGetSymbolAddress(&p, g_Cpart);  float* pCp   = (float*)p;
    cudaGetSymbolAddress(&p, g_C);      float* pC    = (float*)p;
    cudaGetSymbolAddress(&p, g_GT);     float* pGT   = (float*)p;

    cudaFuncSetAttribute(k_final, cudaFuncAttributeMaxDynamicSharedMemorySize, 111872);

    // batch-independent chain
    k_gt<<<dim3(9, 64), 256>>>(gW);
    k_cfcfs<<<256, 256>>>(cm, cnW, cnb, caW);
    k_csum<<<64, 256>>>();
    k_att<<<256, 256>>>(oaW);
    k_att2<<<512, 256>>>(ntW);
    // C = att2 @ G[:,64:]^T   (split-K=16, deterministic reduce)
    sgemm_nt<<<dim3(33, 1, 16), 256>>>(patt2, gW, nullptr, pCp,
                                       2112, 2048, 2048, 2112, 64, 0, 64 * 2112);
    k_redC<<<528, 256>>>();

    // batch trunk
    sgemm_nt<<<dim3(16, 8, 1), 256>>>(x, fiW, fib, ph1, 1024, 2000, 2000, 2000, 0, 1, 0);
    // GEMM2 split-K=8 (partials) + reduce with bias+relu
    sgemm_nt<<<dim3(2, 8, 8), 256>>>(ph1, f1W, nullptr, ph2p, 128, 1024, 1024, 1024, 0, 0, 65536);
    k_redH<<<256, 256>>>(f1b);
    sgemm_nt<<<dim3(64, 8, 1), 256>>>(ph2, o1W, o1b, phid, 4096, 128, 128, 128, 0, 1, 0);

    // fused final
    k_final<<<256, 256, 111872>>>(ntW, pGT, pC, omW, omb, pa, out);
}

// round 8
// speedup vs baseline: 2.2003x; 1.0323x over previous
#include <cuda_runtime.h>
#include <math.h>
#include <stdint.h>

// ---------------- scratch (static device globals; no allocation) ----------------
__device__ float g_h1p[5 * 512 * 1024];     // gemm1 split-K partials
__device__ float g_h1[512 * 1024];
__device__ float g_h2p[8 * 512 * 128];
__device__ float g_h2[512 * 128];
__device__ float g_hidden[512 * 4096];      // [b][o*64+d]
__device__ float g_cfs[64 * 64 * 32];       // [x][y][h]
__device__ float g_csum[64 * 32];
__device__ float g_att[64 * 2048];          // [o][i*32+g]
__device__ float g_att2[64 * 2048];         // [o][j]
__device__ float g_Cpart[16 * 64 * 2112];
__device__ float g_C[64 * 2112];            // [o][e]
__device__ float g_GT[64 * 2112];           // [d][e] = G[e][d]

typedef unsigned long long ull;

__device__ __forceinline__ ull pack2(float x, float y) {
    ull r; asm("mov.b64 %0,{%1,%2};" : "=l"(r) : "f"(x), "f"(y)); return r;
}
__device__ __forceinline__ void ffma2(ull& d, ull a, ull b) {
    asm("fma.rn.f32x2 %0,%1,%2,%0;" : "+l"(d) : "l"(a), "l"(b));
}
__device__ __forceinline__ float2 unpack2(ull v) {
    float2 r; asm("mov.b64 {%0,%1},%2;" : "=f"(r.x), "=f"(r.y) : "l"(v)); return r;
}
__device__ __forceinline__ float eluf(float x) { return x > 0.f ? x : expm1f(x); }
__device__ __forceinline__ float rcpf(float x) {
    float r; asm("rcp.approx.f32 %0,%1;" : "=f"(r) : "f"(x)); return r;
}
__device__ __forceinline__ void cpasync16(uint32_t s, const void* g) {
    asm volatile("cp.async.ca.shared.global [%0], [%1], 16;" :: "r"(s), "l"(g));
}
__device__ __forceinline__ void cpcommit() { asm volatile("cp.async.commit_group;"); }
__device__ __forceinline__ void cpwait0() { asm volatile("cp.async.wait_group 0;"); }

// ---------------- device sgemm (NT, double-buffered, f32x2) ---------------------
// C = act(A[M,K]*B[N,K]^T + bias); 64x64 tile, 256 thr, 4x4/thread; dsm: 4352 floats
__device__ __forceinline__ void dev_sgemm(
    float* dsm, int bx, int by, int bz, int nz,
    const float* __restrict__ A, const float* __restrict__ B,
    const float* __restrict__ bias, float* __restrict__ C,
    int N, int K, int lda, int ldb, int koffB, int relu, int zstride) {
    float* As = dsm;            // 2 buffers x 1088
    float* Bs = dsm + 2176;
    int t = threadIdx.x;
    int tx = t & 15, ty = t >> 4;
    int row0 = by * 64, col0 = bx * 64;
    int kPer = K / nz;
    int k0 = bz * kPer;
    const float* Ap = A + (size_t)(row0 + ty) * lda + k0 + tx;
    const float* Bp = B + (size_t)(col0 + ty) * ldb + koffB + k0 + tx;
    float ra[4], rb[4];
#pragma unroll
    for (int q = 0; q < 4; q++) {
        ra[q] = Ap[(size_t)q * 16 * lda];
        rb[q] = Bp[(size_t)q * 16 * ldb];
    }
#pragma unroll
    for (int q = 0; q < 4; q++) {
        As[tx * 68 + ty + q * 16] = ra[q];
        Bs[tx * 68 + ty + q * 16] = rb[q];
    }
    __syncthreads();
    ull acc[4][2] = {};
    int buf = 0;
    for (int kb = 16; kb <= kPer; kb += 16) {
        if (kb < kPer) {
#pragma unroll
            for (int q = 0; q < 4; q++) {
                ra[q] = Ap[kb + (size_t)q * 16 * lda];
                rb[q] = Bp[kb + (size_t)q * 16 * ldb];
            }
        }
#pragma unroll
        for (int kk = 0; kk < 16; kk++) {
            float4 av = *(const float4*)&As[buf * 1088 + kk * 68 + ty * 4];
            ulonglong2 bp = *(const ulonglong2*)&Bs[buf * 1088 + kk * 68 + tx * 4];
            ull a0 = pack2(av.x, av.x), a1 = pack2(av.y, av.y);
            ull a2 = pack2(av.z, av.z), a3 = pack2(av.w, av.w);
            ffma2(acc[0][0], a0, bp.x); ffma2(acc[0][1], a0, bp.y);
            ffma2(acc[1][0], a1, bp.x); ffma2(acc[1][1], a1, bp.y);
            ffma2(acc[2][0], a2, bp.x); ffma2(acc[2][1], a2, bp.y);
            ffma2(acc[3][0], a3, bp.x); ffma2(acc[3][1], a3, bp.y);
        }
        if (kb < kPer) {
            int nb = buf ^ 1;
#pragma unroll
            for (int q = 0; q < 4; q++) {
                As[nb * 1088 + tx * 68 + ty + q * 16] = ra[q];
                Bs[nb * 1088 + tx * 68 + ty + q * 16] = rb[q];
            }
            __syncthreads();
            buf = nb;
        }
    }
#pragma unroll
    for (int i = 0; i < 4; i++) {
        int m = row0 + ty * 4 + i;
#pragma unroll
        for (int j = 0; j < 2; j++) {
            float2 v = unpack2(acc[i][j]);
            int n = col0 + tx * 4 + 2 * j;
            if (bias) { v.x += bias[n]; v.y += bias[n + 1]; }
            if (relu) { v.x = fmaxf(v.x, 0.f); v.y = fmaxf(v.y, 0.f); }
            float* dst = C + (size_t)zstride * bz + (size_t)m * N + n;
            dst[0] = v.x;
            dst[1] = v.y;
        }
    }
}

// ---------------- device cfcfs: 16 pairs per block ------------------------------
__device__ __forceinline__ void dev_cfcfs(
    float* cawT, int pb, const float* __restrict__ cm,
    const float* __restrict__ cw, const float* __restrict__ cb,
    const float* __restrict__ caw) {
    __shared__ float sc[256], red[8], sp[256], scm[128];
    int t = threadIdx.x;
    int f = t >> 5, g = t & 31;
#pragma unroll
    for (int q = 0; q < 32; q++) {
        int l = t + q * 256;
        int ff = l >> 10, r = l & 1023, gg = r >> 5, h = r & 31;
        cawT[ff * 1056 + h * 33 + gg] = caw[l];
    }
    if (t < 128) scm[t] = cm[pb * 128 + t];
    float cwv = cw[t], cbv = cb[t];
    __syncthreads();
    for (int p = 0; p < 16; p++) {
        float m = scm[p * 8 + f];
        float v = eluf(fmaf(m, cwv, cbv));
        sc[t] = v;
        float r = expf(eluf(v));
#pragma unroll
        for (int off = 16; off; off >>= 1) r += __shfl_xor_sync(0xffffffffu, r, off);
        if (g == 0) red[f] = r;
        __syncthreads();
        float sden = 0.f;
#pragma unroll
        for (int q = 0; q < 8; q++) sden += red[q];
        float lin = 0.f;
#pragma unroll
        for (int h = 0; h < 32; h++) lin = fmaf(sc[f * 32 + h], cawT[f * 1056 + h * 33 + g], lin);
        float E = expf(eluf(v));
        sp[t] = eluf(E * lin / sden);
        __syncthreads();
        if (t < 32) {
            float sum = 0.f;
#pragma unroll
            for (int ff2 = 0; ff2 < 8; ff2++) sum += sp[ff2 * 32 + t];
            g_cfs[(pb * 16 + p) * 32 + t] = eluf(sum * 0.125f);
        }
        __syncthreads();
    }
}

// ---------------- fat1: gemm1 split-K=5 | cfcfs | GT transpose ------------------
__global__ __launch_bounds__(256) void fat1(
    const float* __restrict__ x, const float* __restrict__ fiW,
    const float* __restrict__ cm, const float* __restrict__ cw,
    const float* __restrict__ cb, const float* __restrict__ caw,
    const float* __restrict__ G) {
    extern __shared__ __align__(16) float dsm[];
    int b = blockIdx.x;
    if (b < 640) {
        int bx = b % 16, by = (b / 16) % 8, bz = b / 128;
        dev_sgemm(dsm, bx, by, bz, 5, x, fiW, nullptr, g_h1p,
                  1024, 2000, 2000, 2000, 0, 0, 524288);
    } else if (b < 896) {
        dev_cfcfs(dsm, b - 640, cm, cw, cb, caw);
    } else {
        int i = (b - 896) * 256 + threadIdx.x;   // 135168
        int d = i / 2112, e = i % 2112;
        g_GT[i] = G[(size_t)e * 2112 + d];
    }
}

// ---------------- fat2: redH1 (+bias+relu) | csum -------------------------------
__global__ __launch_bounds__(256) void fat2(const float* __restrict__ fib) {
    int b = blockIdx.x;
    int t = threadIdx.x;
    if (b < 2048) {
        int idx = b * 256 + t;                   // 524288
        float s = 0.f;
#pragma unroll
        for (int z = 0; z < 5; z++) s += g_h1p[z * 524288 + idx];
        g_h1[idx] = fmaxf(s + fib[idx & 1023], 0.f);
    } else {
        int xq = b - 2048;                       // 64
        int ys = t >> 5, h = t & 31;
        float s = 0.f;
        for (int y = ys; y < 64; y += 8) s += expf(eluf(g_cfs[(xq * 64 + y) * 32 + h]));
        __shared__ float r[256];
        r[t] = s;
        __syncthreads();
        if (t < 32) {
            float a = 0.f;
#pragma unroll
            for (int q = 0; q < 8; q++) a += r[q * 32 + t];
            g_csum[xq * 32 + t] = a;
        }
    }
}

// ---------------- fat3: gemm2 split-K=8 | att ------------------------------------
__global__ __launch_bounds__(256) void fat3(const float* __restrict__ f1W,
                                            const float* __restrict__ oaw) {
    extern __shared__ __align__(16) float dsm[];
    int b = blockIdx.x;
    int t = threadIdx.x;
    if (b < 128) {
        int bx = b % 2, by = (b / 2) % 8, bz = b / 16;
        dev_sgemm(dsm, bx, by, bz, 8, g_h1, f1W, nullptr, g_h2p,
                  128, 1024, 1024, 1024, 0, 0, 65536);
    } else {
        int bq = b - 128;                        // 256
        int i = bq >> 2, og = bq & 3;
        int osub = t >> 5, g = t & 31;
        __shared__ float sw[32 * 33];
        __shared__ float scf[16 * 32];
#pragma unroll
        for (int q = 0; q < 4; q++) {
            int l = t + q * 256;
            int gg = l >> 5, h = l & 31;
            sw[h * 33 + gg] = oaw[i * 1024 + l];
        }
#pragma unroll
        for (int q = 0; q < 2; q++) {
            int l = t + q * 256;
            int op = l >> 5, h = l & 31;
            scf[l] = g_cfs[((og * 16 + op) * 64 + i) * 32 + h];
        }
        __syncthreads();
#pragma unroll
        for (int q = 0; q < 2; q++) {
            int op = osub * 2 + q;
            int o = og * 16 + op;
            float lin = 0.f;
#pragma unroll
            for (int h = 0; h < 32; h++) lin = fmaf(scf[op * 32 + h], sw[h * 33 + g], lin);
            float E = expf(eluf(scf[op * 32 + g]));
            g_att[o * 2048 + i * 32 + g] = E / g_csum[o * 32 + g] * lin;
        }
    }
}

// ---------------- fat4: att2 | redH (+bias+relu) ---------------------------------
__global__ __launch_bounds__(256) void fat4(const float* __restrict__ wnt,
                                            const float* __restrict__ f1b) {
    int b = blockIdx.x;
    int t = threadIdx.x;
    if (b < 512) {
        int idx = b * 256 + t;                   // 131072
        int o = idx >> 11, j = idx & 2047;
        float acc = 0.f;
#pragma unroll 8
        for (int p = 0; p < 64; p++) acc += wnt[o * 64 + p] * g_att[p * 2048 + j];
        g_att2[idx] = acc;
    } else {
        int idx = (b - 512) * 256 + t;           // 65536
        float s = 0.f;
#pragma unroll
        for (int z = 0; z < 8; z++) s += g_h2p[z * 65536 + idx];
        g_h2[idx] = fmaxf(s + f1b[idx & 127], 0.f);
    }
}

// ---------------- fat5: C gemm split-K=16 | gemm3 --------------------------------
__global__ __launch_bounds__(256) void fat5(const float* __restrict__ gW,
                                            const float* __restrict__ o1W,
                                            const float* __restrict__ o1b) {
    extern __shared__ __align__(16) float dsm[];
    int b = blockIdx.x;
    if (b < 528) {
        int bx = b % 33, bz = b / 33;
        dev_sgemm(dsm, bx, 0, bz, 16, g_att2, gW, nullptr, g_Cpart,
                  2112, 2048, 2048, 2112, 64, 0, 135168);
    } else {
        int r = b - 528;                         // 512
        int bx = r % 64, by = r / 64;
        dev_sgemm(dsm, bx, by, 0, 1, g_h2, o1W, o1b, g_hidden,
                  4096, 128, 128, 128, 0, 1, 0);
    }
}

// deterministic split-K reduce for C
__global__ void k_redC() {
    int i = blockIdx.x * 256 + threadIdx.x;     // 135168
    float s = 0.f;
#pragma unroll
    for (int z = 0; z < 16; z++) s += g_Cpart[z * 135168 + i];
    g_C[i] = s;
}

// ---------------- fused final: U + y GEMM + sigmoid + weighted reduce ----------
__global__ __launch_bounds__(256, 2) void k_final(
    const float* __restrict__ Wnt, const float* __restrict__ wout,
    const float* __restrict__ outb, const float* __restrict__ pa,
    float* __restrict__ out) {
    extern __shared__ __align__(16) float smem[];
    float* sUT = smem;               // 8448
    float* sA0 = sUT + 8448;         // 4352
    float* sA1 = sA0 + 4352;         // 4352
    float* sB  = sA1 + 4352;         // 2112
    float* sC0 = sB + 2112;          // 4352
    float* sC1 = sC0 + 4352;         // 4352
    const float* GT = g_GT;
    const float* Cg = g_C;
    int t = threadIdx.x;
    int tx = t & 15, ty = t >> 4;
    int bpair = blockIdx.x;
    uint32_t sA0u = (uint32_t)__cvta_generic_to_shared(sA0);
    uint32_t sA1u = (uint32_t)__cvta_generic_to_shared(sA1);
    uint32_t sC0u = (uint32_t)__cvta_generic_to_shared(sC0);
    uint32_t sC1u = (uint32_t)__cvta_generic_to_shared(sC1);

    // prefetch G tile 0 -> sA1 (overlaps the whole U phase)
#pragma unroll
    for (int q = 0; q < 4; q++) {
        int u = t + q * 256;
        int d = u >> 4, e4 = u & 15;
        cpasync16(sA1u + (d * 68 + e4 * 4) * 4, GT + (size_t)d * 2112 + e4 * 4);
    }
    cpcommit();

    // stage Wnt transposed: sA0[p][o]
#pragma unroll
    for (int q = 0; q < 16; q++) {
        int l = t + q * 256;
        int o = l >> 6, p = l & 63;
        sA0[p * 68 + o] = Wnt[l];
    }

    for (int bb = 0; bb < 2; bb++) {
        const float4* hid = (const float4*)(g_hidden + (size_t)(2 * bpair + bb) * 4096);
#pragma unroll
        for (int q = 0; q < 4; q++) {
            int l4 = t + q * 256;
            int p = l4 >> 4, d = (l4 & 15) * 4;
            *(float4*)&sC0[p * 68 + d] = hid[l4];
        }
        __syncthreads();
        ull uacc[4][2] = {};
#pragma unroll 8
        for (int p = 0; p < 64; p++) {
            float4 av = *(const float4*)&sA0[p * 68 + ty * 4];
            ulonglong2 bp2 = *(const ulonglong2*)&sC0[p * 68 + tx * 4];
            ull a0 = pack2(av.x, av.x), a1 = pack2(av.y, av.y);
            ull a2 = pack2(av.z, av.z), a3 = pack2(av.w, av.w);
            ffma2(uacc[0][0], a0, bp2.x); ffma2(uacc[0][1], a0, bp2.y);
            ffma2(uacc[1][0], a1, bp2.x); ffma2(uacc[1][1], a1, bp2.y);
            ffma2(uacc[2][0], a2, bp2.x); ffma2(uacc[2][1], a2, bp2.y);
            ffma2(uacc[3][0], a3, bp2.x); ffma2(uacc[3][1], a3, bp2.y);
        }
#pragma unroll
        for (int i = 0; i < 4; i++) {
            int o = ty * 4 + i;
#pragma unroll
            for (int j = 0; j < 2; j++) {
                float2 v = unpack2(uacc[i][j]);
                int d = tx * 4 + 2 * j;
                sUT[d * 132 + bb * 64 + o] = v.x;
                sUT[(d + 1) * 132 + bb * 64 + o] = v.y;
            }
        }
        __syncthreads();
    }

    // sC0 free now: prefetch C tile 0
#pragma unroll
    for (int q = 0; q < 4; q++) {
        int u = t + q * 256;
        int o = u >> 4, e4 = u & 15;
        cpasync16(sC0u + (o * 68 + e4 * 4) * 4, Cg + (size_t)o * 2112 + e4 * 4);
    }
    cpcommit();

    // stage wout
    for (int l = t; l < 2112; l += 256) sB[l] = wout[l];

    float zacc[8] = {0.f, 0.f, 0.f, 0.f, 0.f, 0.f, 0.f, 0.f};
    int r0 = ty * 8, e0 = tx * 4;

    for (int et = 0; et < 33; et++) {
        cpwait0();
        __syncthreads();
        float* gbuf = (et & 1) ? sA0 : sA1;
        float* cbuf = (et & 1) ? sC1 : sC0;
        if (et < 32) {
            uint32_t gd = (et & 1) ? sA1u : sA0u;
            uint32_t cd = (et & 1) ? sC0u : sC1u;
            const float* gsrc = GT + (et + 1) * 64;
            const float* csrc = Cg + (et + 1) * 64;
#pragma unroll
            for (int q = 0; q < 4; q++) {
                int u = t + q * 256;
                int r = u >> 4, e4 = u & 15;
                cpasync16(gd + (r * 68 + e4 * 4) * 4, gsrc + (size_t)r * 2112 + e4 * 4);
                cpasync16(cd + (r * 68 + e4 * 4) * 4, csrc + (size_t)r * 2112 + e4 * 4);
            }
            cpcommit();
        }
        ull yacc[4][4] = {};
#pragma unroll 4
        for (int d = 0; d < 64; d++) {
            const float* put = &sUT[d * 132 + r0];
            ulonglong2 up0 = *(const ulonglong2*)(put);
            ulonglong2 up1 = *(const ulonglong2*)(put + 4);
            float4 gv = *(const float4*)&gbuf[d * 68 + e0];
            ull g0 = pack2(gv.x, gv.x), g1 = pack2(gv.y, gv.y);
            ull g2 = pack2(gv.z, gv.z), g3 = pack2(gv.w, gv.w);
            ffma2(yacc[0][0], up0.x, g0); ffma2(yacc[0][1], up0.x, g1);
            ffma2(yacc[0][2], up0.x, g2); ffma2(yacc[0][3], up0.x, g3);
            ffma2(yacc[1][0], up0.y, g0); ffma2(yacc[1][1], up0.y, g1);
            ffma2(yacc[1][2], up0.y, g2); ffma2(yacc[1][3], up0.y, g3);
            ffma2(yacc[2][0], up1.x, g0); ffma2(yacc[2][1], up1.x, g1);
            ffma2(yacc[2][2], up1.x, g2); ffma2(yacc[2][3], up1.x, g3);
            ffma2(yacc[3][0], up1.y, g0); ffma2(yacc[3][1], up1.y, g1);
            ffma2(yacc[3][2], up1.y, g2); ffma2(yacc[3][3], up1.y, g3);
        }
        float4 wv = *(const float4*)&sB[et * 64 + e0];
        float wj[4] = {wv.x, wv.y, wv.z, wv.w};
#pragma unroll
        for (int rp = 0; rp < 4; rp++) {
            int rA = r0 + 2 * rp;
            int oA = rA & 63, oB = (rA + 1) & 63;
            float4 cA = *(const float4*)&cbuf[oA * 68 + e0];
            float4 cB = *(const float4*)&cbuf[oB * 68 + e0];
            float cAj[4] = {cA.x, cA.y, cA.z, cA.w};
            float cBj[4] = {cB.x, cB.y, cB.z, cB.w};
#pragma unroll
            for (int j = 0; j < 4; j++) {
                float2 y = unpack2(yacc[rp][j]);
                float ya = y.x + cAj[j];
                float yb = y.y + cBj[j];
                zacc[2 * rp]     += wj[j] * rcpf(1.f + __expf(-ya));
                zacc[2 * rp + 1] += wj[j] * rcpf(1.f + __expf(-yb));
            }
        }
    }

    __syncthreads();
#pragma unroll
    for (int i = 0; i < 8; i++) sA0[(r0 + i) * 16 + tx] = zacc[i];
    __syncthreads();
    if (t < 128) {
        float z = 0.f;
#pragma unroll
        for (int q = 0; q < 16; q++) z += sA0[t * 16 + q];
        z += outb[0];
        float a = pa[0];
        out[bpair * 128 + t] = z >= 0.f ? z : a * z;
    }
}

// ---------------- launcher ----------------
extern "C" void kernel_launch(void* const* d_in, const int* in_sizes, int n_in,
                              void* d_out, int out_size) {
    const float* x   = (const float*)d_in[0];
    const float* fiW = (const float*)d_in[1];
    const float* fib = (const float*)d_in[2];
    const float* f1W = (const float*)d_in[3];
    const float* f1b = (const float*)d_in[4];
    const float* o1W = (const float*)d_in[5];
    const float* o1b = (const float*)d_in[6];
    const float* cnW = (const float*)d_in[7];
    const float* cnb = (const float*)d_in[8];
    const float* caW = (const float*)d_in[9];
    const float* oaW = (const float*)d_in[10];
    const float* ntW = (const float*)d_in[11];
    const float* gW  = (const float*)d_in[12];
    const float* omW = (const float*)d_in[13];
    const float* omb = (const float*)d_in[14];
    const float* pa  = (const float*)d_in[15];
    const float* cm  = (const float*)d_in[16];
    float* out = (float*)d_out;

    cudaFuncSetAttribute(k_final, cudaFuncAttributeMaxDynamicSharedMemorySize, 111872);

    // fat1: gemm1 split-K=5 (640) | cfcfs (256) | GT transpose (528)
    fat1<<<1424, 256, 33792>>>(x, fiW, cm, cnW, cnb, caW, gW);
    // fat2: redH1+bias+relu (2048) | csum (64)
    fat2<<<2112, 256>>>(fib);
    // fat3: gemm2 split-K=8 (128) | att (256)
    fat3<<<384, 256, 17408>>>(f1W, oaW);
    // fat4: att2 (512) | redH+bias+relu (256)
    fat4<<<768, 256>>>(ntW, f1b);
    // fat5: C gemm split-K=16 (528) | gemm3 (512)
    fat5<<<1040, 256, 17408>>>(gW, o1W, o1b);
    k_redC<<<528, 256>>>();
    k_final<<<256, 256, 111872>>>(ntW, omW, omb, pa, out);
}